// round 3
// baseline (speedup 1.0000x reference)
#include <cuda_runtime.h>
#include <cstdint>

#define B_ 8
#define L_ 8192
#define H_ 128
#define N_ 32
#define G_ 256   /* 2H */

typedef unsigned long long ull;

// Scratch (static __device__ arrays: no allocation anywhere)
__device__ float4 g_wk[H_ * N_];                 // {w_re, w_im, k_re, k_im} per (h,n)
__device__ float  g_y[(size_t)B_ * H_ * L_];     // post-GELU activations, (B,H,L)
__device__ float  g_wt[H_ * G_];                 // out_w transposed: [k][g]
__device__ float  g_pooled[B_ * H_];             // sum over l of GLU output

__device__ __forceinline__ ull fma2(ull a, ull b, ull c) {
    ull d; asm("fma.rn.f32x2 %0,%1,%2,%3;" : "=l"(d) : "l"(a), "l"(b), "l"(c)); return d;
}
__device__ __forceinline__ ull pack2(float x, float y) {
    ull d; asm("mov.b64 %0,{%1,%2};" : "=l"(d) : "f"(x), "f"(y)); return d;
}
__device__ __forceinline__ float2 unpack2(ull a) {
    float2 r; asm("mov.b64 {%0,%1},%2;" : "=f"(r.x), "=f"(r.y) : "l"(a)); return r;
}

// ---------------------------------------------------------------------------
// Setup: per-(h,n) discretized SSM params; transpose out_w; zero pooled accum.
// ---------------------------------------------------------------------------
__global__ void setup_kernel(const float* __restrict__ log_dt,
                             const float* __restrict__ log_A_real,
                             const float* __restrict__ A_imag,
                             const float* __restrict__ C_re,
                             const float* __restrict__ C_im,
                             const float* __restrict__ out_w) {
    int i = blockIdx.x * blockDim.x + threadIdx.x;
    if (i < G_ * H_) {
        int k = i & (H_ - 1);
        int g = i >> 7;
        g_wt[k * G_ + g] = out_w[i];            // out_w row-major (2H,H): i = g*H + k
    }
    if (i < H_ * N_) {
        int h = i >> 5;
        float dt = expf(log_dt[h]);
        float ar = -expf(log_A_real[i]);
        float ai = A_imag[i];
        float er = expf(dt * ar);
        float si, co;
        sincosf(dt * ai, &si, &co);
        float wr = er * co, wi = er * si;       // w = exp(dt*A)
        float inv = 1.f / (ar * ar + ai * ai);
        float dr = wr - 1.f;
        float qr = (dr * ar + wi * ai) * inv;   // (w-1)/A
        float qi = (wi * ar - dr * ai) * inv;
        float cr = C_re[i], ci = C_im[i];
        float kr = 2.f * (cr * qr - ci * qi);   // 2*C*(w-1)/A
        float ki = 2.f * (cr * qi + ci * qr);
        g_wk[i] = make_float4(wr, wi, kr, ki);
    }
    if (i < B_ * H_) g_pooled[i] = 0.f;
}

// ---------------------------------------------------------------------------
// S4D scan: warp per (b,h), lane = state n. Encoder fused on the fly.
// Per step: broadcast u, complex state update, per-lane contribution STS'd to
// smem[n][t]; every 32 steps each lane transposes-and-sums column lane, adds
// D*u skip, applies tanh-GELU, writes y coalesced.
// ---------------------------------------------------------------------------
__global__ void __launch_bounds__(256) scan_kernel(const float* __restrict__ x,
                                                   const float* __restrict__ enc_w,
                                                   const float* __restrict__ enc_b,
                                                   const float* __restrict__ D) {
    __shared__ float sbuf[8][N_][33];   // [warp][n][t], stride-33 pad: conflict-free
    int tid = threadIdx.x;
    int wid = tid >> 5, lane = tid & 31;
    int warp = blockIdx.x * 8 + wid;    // 0..1023
    int b = warp >> 7, h = warp & 127;

    float4 wk = g_wk[h * N_ + lane];
    float wr = wk.x, wi = wk.y, kr = wk.z;
    float nwi = -wk.y, nki = -wk.w;
    float e0 = enc_w[h], e1 = enc_w[H_ + h], eb = enc_b[h], Dh = D[h];
    const float2* xb = reinterpret_cast<const float2*>(x) + (size_t)b * L_;
    float* yout = g_y + ((size_t)b * H_ + h) * L_;
    float (*sw)[33] = sbuf[wid];

    float sre = 0.f, sim = 0.f;
    for (int l0 = 0; l0 < L_; l0 += 32) {
        float2 xv = xb[l0 + lane];
        float um = fmaf(e1, xv.y, fmaf(e0, xv.x, eb));   // u[b,h,l0+lane]
        #pragma unroll
        for (int t = 0; t < 32; ++t) {
            float u = __shfl_sync(0xffffffffu, um, t);
            float tr = fmaf(wr, sre, u);
            float ti = wr * sim;
            float nre = fmaf(nwi, sim, tr);   // s_re' = wr*s_re - wi*s_im + u
            sim = fmaf(wi, sre, ti);          // s_im' = wi*s_re + wr*s_im
            sre = nre;
            sw[lane][t] = fmaf(kr, sre, nki * sim);   // Re(k * s)
        }
        __syncwarp();
        float y0 = 0.f, y1 = 0.f, y2 = 0.f, y3 = 0.f;
        #pragma unroll
        for (int n = 0; n < 32; n += 4) {
            y0 += sw[n + 0][lane];
            y1 += sw[n + 1][lane];
            y2 += sw[n + 2][lane];
            y3 += sw[n + 3][lane];
        }
        float yv = (y0 + y1) + (y2 + y3) + Dh * um;
        // JAX default gelu (approximate=True, tanh form)
        float cc = fmaf(0.044715f * yv, yv * yv, yv);
        float gl = 0.5f * yv * (1.f + tanhf(0.7978845608f * cc));
        yout[l0 + lane] = gl;
        __syncwarp();
    }
}

// ---------------------------------------------------------------------------
// GLU projection + pool: z = out_w @ y (per b,l), GLU(a, gate), sum over l.
// Block: (b, 512-l region), 256 threads, thread tile = 8 g-rows x 8 l (4 GLU
// pairs), accumulators packed f32x2 along l -> fma.rn.f32x2 (2 MACs/instr).
// ---------------------------------------------------------------------------
__global__ void __launch_bounds__(256) glu_kernel(const float* __restrict__ out_b) {
    __shared__ float ys[H_ * 68];       // y tile [h][64 l], pad 68
    int tid = threadIdx.x;
    int tx = tid & 7;                   // l-group (8 l's)
    int ty = tid >> 3;                  // 0..31 -> g rows 4*ty..4*ty+3 (+128 gates)
    int b = blockIdx.y;
    int lbase = blockIdx.x * 512;

    float bA[4], bG[4];
    #pragma unroll
    for (int i = 0; i < 4; i++) { bA[i] = out_b[4 * ty + i]; bG[i] = out_b[128 + 4 * ty + i]; }
    float pool[4] = {0.f, 0.f, 0.f, 0.f};
    const float* ybase = g_y + (size_t)b * H_ * L_;

    for (int c = 0; c < 8; ++c) {
        int l0 = lbase + c * 64;
        for (int i = tid; i < H_ * 16; i += 256) {
            int hh = i >> 4, lq = i & 15;
            float4 v = *reinterpret_cast<const float4*>(ybase + (size_t)hh * L_ + l0 + lq * 4);
            *reinterpret_cast<float4*>(ys + hh * 68 + lq * 4) = v;
        }
        __syncthreads();

        ull acc[8][4];
        #pragma unroll
        for (int r = 0; r < 8; r++)
            #pragma unroll
            for (int j = 0; j < 4; j++) acc[r][j] = 0ull;

        #pragma unroll 4
        for (int k = 0; k < H_; ++k) {
            float4 aA = *reinterpret_cast<const float4*>(g_wt + k * G_ + 4 * ty);
            float4 aG = *reinterpret_cast<const float4*>(g_wt + k * G_ + 128 + 4 * ty);
            const ull* yp = reinterpret_cast<const ull*>(ys + k * 68 + 8 * tx);
            ull v0 = yp[0], v1 = yp[1], v2 = yp[2], v3 = yp[3];
            ull pa;
            pa = pack2(aA.x, aA.x); acc[0][0]=fma2(pa,v0,acc[0][0]); acc[0][1]=fma2(pa,v1,acc[0][1]); acc[0][2]=fma2(pa,v2,acc[0][2]); acc[0][3]=fma2(pa,v3,acc[0][3]);
            pa = pack2(aA.y, aA.y); acc[1][0]=fma2(pa,v0,acc[1][0]); acc[1][1]=fma2(pa,v1,acc[1][1]); acc[1][2]=fma2(pa,v2,acc[1][2]); acc[1][3]=fma2(pa,v3,acc[1][3]);
            pa = pack2(aA.z, aA.z); acc[2][0]=fma2(pa,v0,acc[2][0]); acc[2][1]=fma2(pa,v1,acc[2][1]); acc[2][2]=fma2(pa,v2,acc[2][2]); acc[2][3]=fma2(pa,v3,acc[2][3]);
            pa = pack2(aA.w, aA.w); acc[3][0]=fma2(pa,v0,acc[3][0]); acc[3][1]=fma2(pa,v1,acc[3][1]); acc[3][2]=fma2(pa,v2,acc[3][2]); acc[3][3]=fma2(pa,v3,acc[3][3]);
            pa = pack2(aG.x, aG.x); acc[4][0]=fma2(pa,v0,acc[4][0]); acc[4][1]=fma2(pa,v1,acc[4][1]); acc[4][2]=fma2(pa,v2,acc[4][2]); acc[4][3]=fma2(pa,v3,acc[4][3]);
            pa = pack2(aG.y, aG.y); acc[5][0]=fma2(pa,v0,acc[5][0]); acc[5][1]=fma2(pa,v1,acc[5][1]); acc[5][2]=fma2(pa,v2,acc[5][2]); acc[5][3]=fma2(pa,v3,acc[5][3]);
            pa = pack2(aG.z, aG.z); acc[6][0]=fma2(pa,v0,acc[6][0]); acc[6][1]=fma2(pa,v1,acc[6][1]); acc[6][2]=fma2(pa,v2,acc[6][2]); acc[6][3]=fma2(pa,v3,acc[6][3]);
            pa = pack2(aG.w, aG.w); acc[7][0]=fma2(pa,v0,acc[7][0]); acc[7][1]=fma2(pa,v1,acc[7][1]); acc[7][2]=fma2(pa,v2,acc[7][2]); acc[7][3]=fma2(pa,v3,acc[7][3]);
        }
        __syncthreads();

        // GLU + partial pool (epilogue, registers only)
        #pragma unroll
        for (int i = 0; i < 4; i++) {
            float s = 0.f;
            #pragma unroll
            for (int j = 0; j < 4; j++) {
                float2 za = unpack2(acc[i][j]);
                float2 zg = unpack2(acc[4 + i][j]);
                float a0 = za.x + bA[i], a1 = za.y + bA[i];
                float g0 = zg.x + bG[i], g1 = zg.y + bG[i];
                s += a0 * (1.f / (1.f + __expf(-g0)));
                s += a1 * (1.f / (1.f + __expf(-g1)));
            }
            pool[i] += s;
        }
    }
    #pragma unroll
    for (int i = 0; i < 4; i++)
        atomicAdd(&g_pooled[b * H_ + 4 * ty + i], pool[i]);
}

// ---------------------------------------------------------------------------
// Decode: out[b] = (pooled_sum[b,:]/L) . dec_w + dec_b
// ---------------------------------------------------------------------------
__global__ void decode_kernel(const float* __restrict__ dec_w,
                              const float* __restrict__ dec_b,
                              float* __restrict__ out) {
    int wid = threadIdx.x >> 5, lane = threadIdx.x & 31;
    int b = wid;                        // 8 warps, one per batch
    float p = 0.f;
    #pragma unroll
    for (int i = 0; i < 4; i++) {
        int h = lane + 32 * i;
        p += g_pooled[b * H_ + h] * dec_w[h];
    }
    p += __shfl_xor_sync(0xffffffffu, p, 16);
    p += __shfl_xor_sync(0xffffffffu, p, 8);
    p += __shfl_xor_sync(0xffffffffu, p, 4);
    p += __shfl_xor_sync(0xffffffffu, p, 2);
    p += __shfl_xor_sync(0xffffffffu, p, 1);
    if (lane == 0) out[b] = p * (1.f / (float)L_) + dec_b[0];
}

// ---------------------------------------------------------------------------
extern "C" void kernel_launch(void* const* d_in, const int* in_sizes, int n_in,
                              void* d_out, int out_size) {
    const float* x      = (const float*)d_in[0];
    const float* enc_w  = (const float*)d_in[1];
    const float* enc_b  = (const float*)d_in[2];
    const float* log_dt = (const float*)d_in[3];
    const float* log_A  = (const float*)d_in[4];
    const float* A_im   = (const float*)d_in[5];
    const float* C_re   = (const float*)d_in[6];
    const float* C_im   = (const float*)d_in[7];
    const float* D      = (const float*)d_in[8];
    const float* out_w  = (const float*)d_in[9];
    const float* out_b  = (const float*)d_in[10];
    const float* dec_w  = (const float*)d_in[11];
    const float* dec_b  = (const float*)d_in[12];
    float* out = (float*)d_out;

    setup_kernel<<<128, 256>>>(log_dt, log_A, A_im, C_re, C_im, out_w);
    scan_kernel<<<128, 256>>>(x, enc_w, enc_b, D);
    glu_kernel<<<dim3(16, 8), 256>>>(out_b);
    decode_kernel<<<1, 256>>>(dec_w, dec_b, out);
}